// round 4
// baseline (speedup 1.0000x reference)
#include <cuda_runtime.h>
#include <cuda_fp16.h>
#include <cstdint>

// Problem dims
#define MDIM 8192   // B*S
#define NDIM 4096
#define KDIM 4096

// GEMM tiling
#define TM 128
#define TN 128
#define KC 64                        // 64 fp16 = 128B per row (swizzle atom)
#define NSTAGE 4
#define NK (KDIM / KC)               // 64
#define A_TILE_BYTES (TM * KC * 2)   // 16384
#define B_TILE_BYTES (TN * KC * 2)   // 16384
#define STAGE_BYTES (A_TILE_BYTES + B_TILE_BYTES)   // 32768
#define SMEM_DYN (NSTAGE * STAGE_BYTES)             // 131072

// Scratch (allocation-free rule: __device__ globals)
__device__ uint4 g_A16[(MDIM * (size_t)KDIM) / 8];   // fp16 A, [M, K]
__device__ uint4 g_W16[(NDIM * (size_t)KDIM) / 8];   // fp16 W^T, [N, K]

// ---------------------------------------------------------------------------
// helpers
// ---------------------------------------------------------------------------
__device__ __forceinline__ uint32_t smem_u32(const void* p) {
    uint32_t r;
    asm("{ .reg .u64 t; cvta.to.shared.u64 t, %1; cvt.u32.u64 %0, t; }"
        : "=r"(r) : "l"(p));
    return r;
}

__device__ __forceinline__ void cp_async16(uint32_t s, const void* g) {
    asm volatile("cp.async.cg.shared.global [%0], [%1], 16;"
                 :: "r"(s), "l"(__cvta_generic_to_global(g)) : "memory");
}

#define LDM_X4(r, addr)                                                        \
    asm volatile("ldmatrix.sync.aligned.m8n8.x4.shared.b16 {%0,%1,%2,%3}, [%4];" \
                 : "=r"((r)[0]), "=r"((r)[1]), "=r"((r)[2]), "=r"((r)[3])      \
                 : "r"(addr))

__device__ __forceinline__ void mma16816(float* d, const uint32_t* a,
                                         const uint32_t* b) {
    asm volatile(
        "mma.sync.aligned.m16n8k16.row.col.f32.f16.f16.f32 "
        "{%0,%1,%2,%3}, {%4,%5,%6,%7}, {%8,%9}, {%0,%1,%2,%3};"
        : "+f"(d[0]), "+f"(d[1]), "+f"(d[2]), "+f"(d[3])
        : "r"(a[0]), "r"(a[1]), "r"(a[2]), "r"(a[3]), "r"(b[0]), "r"(b[1]));
}

// ---------------------------------------------------------------------------
// Pre-pass 1: A fp32 -> fp16
// ---------------------------------------------------------------------------
__global__ void __launch_bounds__(256) k_aconv(const float* __restrict__ in) {
    size_t i = ((size_t)blockIdx.x * 256 + threadIdx.x) * 8;
    float4 a = *(const float4*)(in + i);
    float4 b = *(const float4*)(in + i + 4);
    union { __half2 h[4]; uint4 u; } pk;
    pk.h[0] = __floats2half2_rn(a.x, a.y);
    pk.h[1] = __floats2half2_rn(a.z, a.w);
    pk.h[2] = __floats2half2_rn(b.x, b.y);
    pk.h[3] = __floats2half2_rn(b.z, b.w);
    g_A16[i >> 3] = pk.u;
}

// ---------------------------------------------------------------------------
// Pre-pass 2: GPTQ int4 dequant -> fp16, transposed to [N, K]
// ---------------------------------------------------------------------------
__global__ void __launch_bounds__(256) k_dequant(const int* __restrict__ qw,
                                                 const float* __restrict__ sc,
                                                 const int* __restrict__ qz) {
    int idx = blockIdx.x * 256 + threadIdx.x;   // over (K/8)*N, n fastest
    int n  = idx & (NDIM - 1);
    int kk = idx >> 12;                         // k/8
    int g  = kk >> 4;                           // group = (kk*8)/128
    int q  = qw[idx];
    int zw = qz[(g << 9) | (n >> 3)];
    float z = (float)((zw >> ((n & 7) << 2)) & 15);
    float s = sc[(g << 12) | n];
    union { __half2 h[4]; uint4 u; } pk;
#pragma unroll
    for (int j = 0; j < 4; ++j) {
        float w0 = ((float)((q >> (8 * j))     & 15) - z) * s;
        float w1 = ((float)((q >> (8 * j + 4)) & 15) - z) * s;
        pk.h[j] = __floats2half2_rn(w0, w1);
    }
    __half* W = (__half*)g_W16;
    *(uint4*)(W + (size_t)n * KDIM + kk * 8) = pk.u;
}

// ---------------------------------------------------------------------------
// Main GEMM: C = A @ W^T + bias + residual
// 128x128 CTA tile, 16 warps (4m x 2n x 2k), warp tile 32x64 over a k32 half,
// mma.sync m16n8k16, 4-stage cp.async pipeline, swizzled 128B smem rows.
// Cross-k reduction through smem at the end.
// ---------------------------------------------------------------------------
__global__ void __launch_bounds__(512, 1)
k_gemm(const float* __restrict__ residual, const float* __restrict__ bias,
       float* __restrict__ out) {
    extern __shared__ char smem_raw[];
    const uint32_t sbase = smem_u32(smem_raw);

    const int tid  = threadIdx.x;
    const int wid  = tid >> 5;
    const int lane = tid & 31;
    const int warp_k = wid & 1;         // 2-way k split
    const int warp_m = (wid >> 1) & 3;  // 4 warps along M (32 rows each)
    const int warp_n = wid >> 3;        // 2 warps along N (64 cols each)

    // L2-friendly raster: supertiles of 8 m-tiles x 32 n-tiles
    const int bid = blockIdx.x;
    const int tm_ = ((bid >> 8) << 3) | (bid & 7);
    const int tn_ = (bid >> 3) & 31;

    const __half* A16 = (const __half*)g_A16;
    const __half* W16 = (const __half*)g_W16;
    const __half* gA = A16 + (size_t)tm_ * TM * KDIM;
    const __half* gB = W16 + (size_t)tn_ * TN * KDIM;

    // ldmatrix per-lane metadata
    const int tileid = lane >> 3, r8 = lane & 7;
    uint32_t aoff[2]; int asw[2];
    const int achk = tileid >> 1;
#pragma unroll
    for (int mt = 0; mt < 2; ++mt) {
        int ar = warp_m * 32 + mt * 16 + ((tileid & 1) << 3) + r8;
        aoff[mt] = (uint32_t)(ar << 7);
        asw[mt] = ar & 7;
    }
    uint32_t boff[4]; int bsw[4];
    const int bchk = tileid & 1;
#pragma unroll
    for (int nt = 0; nt < 4; ++nt) {
        int br = warp_n * 64 + nt * 16 + ((tileid >> 1) << 3) + r8;
        boff[nt] = (uint32_t)(br << 7);
        bsw[nt] = br & 7;
    }

    // Stage loader: 256 rows x 8 sixteen-byte cols = 2048 ops / 512 thr = 4 each
    auto load_stage = [&](int c, int slot) {
        const uint32_t sA = sbase + slot * STAGE_BYTES;
        const __half* pA = gA + c * KC;
        const __half* pB = gB + c * KC;
#pragma unroll
        for (int rep = 0; rep < 4; ++rep) {
            int idx = tid + rep * 512;
            int row = idx >> 3;          // 0..255
            int c16 = idx & 7;
            uint32_t soff = (uint32_t)(row << 7) |
                            (uint32_t)((c16 ^ (row & 7)) << 4);
            const __half* g = (row < TM)
                ? pA + (size_t)row * KDIM + c16 * 8
                : pB + (size_t)(row - TM) * KDIM + c16 * 8;
            cp_async16(sA + soff, g);
        }
    };

    float acc[2][8][4];
#pragma unroll
    for (int mt = 0; mt < 2; ++mt)
#pragma unroll
        for (int nt = 0; nt < 8; ++nt)
#pragma unroll
            for (int j = 0; j < 4; ++j) acc[mt][nt][j] = 0.f;

    // Prologue
#pragma unroll
    for (int c = 0; c < NSTAGE - 1; ++c) {
        load_stage(c, c);
        asm volatile("cp.async.commit_group;" ::: "memory");
    }

#pragma unroll 1
    for (int i = 0; i < NK; ++i) {
        const int slot = i & (NSTAGE - 1);
        asm volatile("cp.async.wait_group 2;" ::: "memory");
        __syncthreads();

        const int c = i + NSTAGE - 1;
        if (c < NK) load_stage(c, c & (NSTAGE - 1));
        asm volatile("cp.async.commit_group;" ::: "memory");

        const uint32_t sA = sbase + slot * STAGE_BYTES;
        const uint32_t sB = sA + A_TILE_BYTES;

#pragma unroll
        for (int s = 0; s < 2; ++s) {   // this warp's 2 k16 steps of its k32 half
            const int sg = warp_k * 2 + s;   // global k16 step within KC=64
            uint32_t a[2][4], b[4][4];
#pragma unroll
            for (int mt = 0; mt < 2; ++mt)
                LDM_X4(a[mt], sA + aoff[mt] +
                              (uint32_t)((((sg << 1) + achk) ^ asw[mt]) << 4));
#pragma unroll
            for (int nt = 0; nt < 4; ++nt)
                LDM_X4(b[nt], sB + boff[nt] +
                              (uint32_t)((((sg << 1) + bchk) ^ bsw[nt]) << 4));
#pragma unroll
            for (int mt = 0; mt < 2; ++mt)
#pragma unroll
                for (int nt = 0; nt < 4; ++nt) {
                    mma16816(acc[mt][2 * nt],     a[mt], b[nt]);
                    mma16816(acc[mt][2 * nt + 1], a[mt], b[nt] + 2);
                }
        }
    }

    // Cross-k reduction: warp_k=1 warps dump acc to smem, warp_k=0 adds.
    asm volatile("cp.async.wait_group 0;" ::: "memory");
    __syncthreads();
    {
        // slot id 0..7 for the (warp_m, warp_n) pair
        const int pslot = (warp_n << 2) | warp_m;
        const uint32_t rbase = sbase + (uint32_t)pslot * 8192;  // 64KB total
        if (warp_k == 1) {
#pragma unroll
            for (int mt = 0; mt < 2; ++mt)
#pragma unroll
                for (int nt = 0; nt < 8; ++nt)
#pragma unroll
                    for (int j = 0; j < 4; ++j) {
                        uint32_t off = rbase +
                            (uint32_t)((((mt << 3) | nt) << 2 | j) << 7) +
                            (uint32_t)(lane << 2);
                        asm volatile("st.shared.f32 [%0], %1;"
                                     :: "r"(off), "f"(acc[mt][nt][j]) : "memory");
                    }
        }
        __syncthreads();
        if (warp_k == 0) {
#pragma unroll
            for (int mt = 0; mt < 2; ++mt)
#pragma unroll
                for (int nt = 0; nt < 8; ++nt)
#pragma unroll
                    for (int j = 0; j < 4; ++j) {
                        uint32_t off = rbase +
                            (uint32_t)((((mt << 3) | nt) << 2 | j) << 7) +
                            (uint32_t)(lane << 2);
                        float v;
                        asm volatile("ld.shared.f32 %0, [%1];"
                                     : "=f"(v) : "r"(off));
                        acc[mt][nt][j] += v;
                    }
        }
    }

    // Epilogue (warp_k = 0 only): fp32 acc + bias + residual -> out
    if (warp_k == 0) {
        const int r  = lane >> 2;
        const int c2 = (lane & 3) * 2;
        const int mbase = tm_ * TM + warp_m * 32;
        const int nbase = tn_ * TN + warp_n * 64;
#pragma unroll
        for (int mt = 0; mt < 2; ++mt) {
#pragma unroll
            for (int half = 0; half < 2; ++half) {   // rows r and r+8
                const size_t m = (size_t)(mbase + mt * 16 + r + half * 8);
                const float* rp = residual + m * NDIM + nbase;
                float* op = out + m * NDIM + nbase;
#pragma unroll
                for (int nt = 0; nt < 8; ++nt) {
                    const int n = nt * 8 + c2;
                    float2 res = *(const float2*)(rp + n);
                    float2 bz  = *(const float2*)(bias + nbase + n);
                    float2 o;
                    o.x = acc[mt][nt][2 * half]     + bz.x + res.x;
                    o.y = acc[mt][nt][2 * half + 1] + bz.y + res.y;
                    *(float2*)(op + n) = o;
                }
            }
        }
    }
}

// ---------------------------------------------------------------------------
extern "C" void kernel_launch(void* const* d_in, const int* in_sizes, int n_in,
                              void* d_out, int out_size) {
    const float* input    = (const float*)d_in[0];   // [2,4096,4096] f32
    const float* residual = (const float*)d_in[1];   // [2,4096,4096] f32
    const int*   qweight  = (const int*)d_in[2];     // [512,4096] i32
    const float* scales   = (const float*)d_in[3];   // [32,4096] f32
    const int*   qzeros   = (const int*)d_in[4];     // [32,512] i32
    const float* bias     = (const float*)d_in[5];   // [4096] f32
    float* out = (float*)d_out;

    cudaFuncSetAttribute(k_gemm, cudaFuncAttributeMaxDynamicSharedMemorySize,
                         SMEM_DYN);

    k_aconv<<<(MDIM * (size_t)KDIM) / 8 / 256, 256>>>(input);
    k_dequant<<<(KDIM / 8) * NDIM / 256, 256>>>(qweight, scales, qzeros);

    const int nblocks = (MDIM / TM) * (NDIM / TN);   // 2048
    k_gemm<<<nblocks, 512, SMEM_DYN>>>(residual, bias, out);
}

// round 5
// speedup vs baseline: 1.0061x; 1.0061x over previous
#include <cuda_runtime.h>
#include <cuda_fp16.h>
#include <cstdint>

// Problem dims
#define MDIM 8192   // B*S
#define NDIM 4096
#define KDIM 4096

// GEMM tiling
#define TM 128
#define TN 128
#define KC 64                        // 64 fp16 = 128B per row (swizzle atom)
#define NSTAGE 3
#define NK (KDIM / KC)               // 64
#define A_TILE_BYTES (TM * KC * 2)   // 16384
#define B_TILE_BYTES (TN * KC * 2)   // 16384
#define STAGE_BYTES (A_TILE_BYTES + B_TILE_BYTES)   // 32768
#define SMEM_DYN (NSTAGE * STAGE_BYTES)             // 98304

// Scratch (allocation-free rule: __device__ global)
__device__ uint4 g_A16[(MDIM * (size_t)KDIM) / 8];   // fp16 A, [M, K]

// ---------------------------------------------------------------------------
// helpers
// ---------------------------------------------------------------------------
__device__ __forceinline__ uint32_t smem_u32(const void* p) {
    uint32_t r;
    asm("{ .reg .u64 t; cvta.to.shared.u64 t, %1; cvt.u32.u64 %0, t; }"
        : "=r"(r) : "l"(p));
    return r;
}

__device__ __forceinline__ void cp_async16(uint32_t s, const void* g) {
    asm volatile("cp.async.cg.shared.global [%0], [%1], 16;"
                 :: "r"(s), "l"(__cvta_generic_to_global(g)) : "memory");
}

#define LDM_X4(r, addr)                                                        \
    asm volatile("ldmatrix.sync.aligned.m8n8.x4.shared.b16 {%0,%1,%2,%3}, [%4];" \
                 : "=r"((r)[0]), "=r"((r)[1]), "=r"((r)[2]), "=r"((r)[3])      \
                 : "r"(addr))

__device__ __forceinline__ void mma16816(float* d, const uint32_t* a,
                                         const uint32_t* b) {
    asm volatile(
        "mma.sync.aligned.m16n8k16.row.col.f32.f16.f16.f32 "
        "{%0,%1,%2,%3}, {%4,%5,%6,%7}, {%8,%9}, {%0,%1,%2,%3};"
        : "+f"(d[0]), "+f"(d[1]), "+f"(d[2]), "+f"(d[3])
        : "r"(a[0]), "r"(a[1]), "r"(a[2]), "r"(a[3]), "r"(b[0]), "r"(b[1]));
}

// ---------------------------------------------------------------------------
// Pre-pass: A fp32 -> fp16
// ---------------------------------------------------------------------------
__global__ void __launch_bounds__(256) k_aconv(const float* __restrict__ in) {
    size_t i = ((size_t)blockIdx.x * 256 + threadIdx.x) * 8;
    float4 a = *(const float4*)(in + i);
    float4 b = *(const float4*)(in + i + 4);
    union { __half2 h[4]; uint4 u; } pk;
    pk.h[0] = __floats2half2_rn(a.x, a.y);
    pk.h[1] = __floats2half2_rn(a.z, a.w);
    pk.h[2] = __floats2half2_rn(b.x, b.y);
    pk.h[3] = __floats2half2_rn(b.z, b.w);
    g_A16[i >> 3] = pk.u;
}

// ---------------------------------------------------------------------------
// Main GEMM with fused in-loop int4 B dequant.
// C = A @ W^T + bias + residual
// 128x128 CTA tile, 8 warps (4m x 2n), warp tile 32x64, mma.sync m16n8k16,
// 3-stage pipeline: A via cp.async, B via LDG(int4 packed) + register
// dequant (fp16 magic) + STS.128 one stage ahead.
// ---------------------------------------------------------------------------
__global__ void __launch_bounds__(256, 2)
k_gemm(const float* __restrict__ residual, const float* __restrict__ bias,
       float* __restrict__ out,
       const int* __restrict__ qw, const float* __restrict__ sc,
       const int* __restrict__ qz) {
    extern __shared__ char smem_raw[];
    const uint32_t sbase = smem_u32(smem_raw);

    const int tid  = threadIdx.x;
    const int wid  = tid >> 5;
    const int lane = tid & 31;
    const int warp_m = wid & 3;   // 4 warps along M (32 rows each)
    const int warp_n = wid >> 2;  // 2 warps along N (64 cols each)

    // L2-friendly raster: supertiles of 8 m-tiles x 32 n-tiles
    const int bid = blockIdx.x;
    const int tm_ = ((bid >> 8) << 3) | (bid & 7);
    const int tn_ = (bid >> 3) & 31;

    const __half* A16 = (const __half*)g_A16;
    const __half* gA = A16 + (size_t)tm_ * TM * KDIM;

    // ---- B dequant per-thread statics: fixed n, two k8-octets base -------
    const int nloc = tid & 127;               // local n (smem B row)
    const int n_g  = tn_ * TN + nloc;         // global n
    const int kk8b = tid >> 7;                // 0 or 1

    // ldmatrix per-lane metadata
    const int tileid = lane >> 3, r8 = lane & 7;
    uint32_t aoff[2]; int asw[2];
    const int achk = tileid >> 1;
#pragma unroll
    for (int mt = 0; mt < 2; ++mt) {
        int ar = warp_m * 32 + mt * 16 + ((tileid & 1) << 3) + r8;
        aoff[mt] = (uint32_t)(ar << 7);
        asw[mt] = ar & 7;
    }
    uint32_t boff[4]; int bsw[4];
    const int bchk = tileid & 1;
#pragma unroll
    for (int nt = 0; nt < 4; ++nt) {
        int br = warp_n * 64 + nt * 16 + ((tileid >> 1) << 3) + r8;
        boff[nt] = (uint32_t)(br << 7);
        bsw[nt] = br & 7;
    }

    // A stage loader: 128 rows x 8 sixteen-byte cols = 1024 ops / 256 thr
    auto load_A = [&](int c, int slot) {
        const uint32_t sA = sbase + slot * STAGE_BYTES;
        const __half* pA = gA + c * KC;
#pragma unroll
        for (int rep = 0; rep < 4; ++rep) {
            int idx = tid + rep * 256;
            int row = idx >> 3;
            int c16 = idx & 7;
            uint32_t soff = (uint32_t)(row << 7) |
                            (uint32_t)((c16 ^ (row & 7)) << 4);
            cp_async16(sA + soff, pA + (size_t)row * KDIM + c16 * 8);
        }
    };

    // scale/zero for group g (one (s, z) per thread — n is fixed)
    auto load_sz = [&](int g, uint32_t& s2r, uint32_t& z2r) {
        float s = __ldg(sc + ((size_t)g << 12) + n_g);
        int zw = __ldg(qz + (g << 9) + (n_g >> 3));
        int z = (zw >> ((n_g & 7) << 2)) & 15;
        __half2 s2 = __float2half2_rn(s);
        __half2 z2 = __float2half2_rn(1024.0f + (float)z);
        s2r = *(uint32_t*)&s2;
        z2r = *(uint32_t*)&z2;
    };

    // LDG packed B for chunk c: 4 int32 per thread (rows kk8b, +2, +4, +6)
    auto ldg_packed = [&](int c, uint32_t* bq) {
#pragma unroll
        for (int rep = 0; rep < 4; ++rep) {
            int k8 = c * 8 + kk8b + 2 * rep;
            bq[rep] = (uint32_t)__ldg(qw + ((size_t)k8 << 12) + n_g);
        }
    };

    // Dequant 4 packed int32 -> 4x STS.128 into B half of stage `slot`
    auto sts_dequant = [&](const uint32_t* bq, uint32_t s2, uint32_t z2,
                           int slot) {
        const uint32_t sB = sbase + slot * STAGE_BYTES + A_TILE_BYTES;
        const __half2 hs = *(const __half2*)&s2;
        const __half2 hz = *(const __half2*)&z2;
#pragma unroll
        for (int rep = 0; rep < 4; ++rep) {
            const int kk8 = kk8b + 2 * rep;
            const uint32_t q = bq[rep];
            uint32_t v[4];
#pragma unroll
            for (int j = 0; j < 4; ++j) {
                uint32_t t = ((q >> (4 * j)) & 0x000F000Fu) | 0x64006400u;
                __half2 h = __hmul2(__hsub2(*(__half2*)&t, hz), hs);
                v[j] = *(uint32_t*)&h;
            }
            uint32_t o0 = __byte_perm(v[0], v[1], 0x5410);
            uint32_t o1 = __byte_perm(v[2], v[3], 0x5410);
            uint32_t o2 = __byte_perm(v[0], v[1], 0x7632);
            uint32_t o3 = __byte_perm(v[2], v[3], 0x7632);
            uint32_t soff = sB + (uint32_t)(nloc << 7) +
                            (uint32_t)((kk8 ^ (nloc & 7)) << 4);
            asm volatile("st.shared.v4.b32 [%0], {%1,%2,%3,%4};"
                         :: "r"(soff), "r"(o0), "r"(o1), "r"(o2), "r"(o3)
                         : "memory");
        }
    };

    float acc[2][8][4];
#pragma unroll
    for (int mt = 0; mt < 2; ++mt)
#pragma unroll
        for (int nt = 0; nt < 8; ++nt)
#pragma unroll
            for (int j = 0; j < 4; ++j) acc[mt][nt][j] = 0.f;

    // ---- Prologue --------------------------------------------------------
    uint32_t cur_s2, cur_z2, pend_s2, pend_z2;
    load_sz(0, cur_s2, cur_z2);
    pend_s2 = cur_s2; pend_z2 = cur_z2;

    uint32_t bq[4];
    ldg_packed(0, bq);
    sts_dequant(bq, cur_s2, cur_z2, 0);    // B chunk 0 -> slot 0
    ldg_packed(1, bq);                      // B chunk 1 regs (STS at iter 0)

    load_A(0, 0);
    asm volatile("cp.async.commit_group;" ::: "memory");
    load_A(1, 1);
    asm volatile("cp.async.commit_group;" ::: "memory");

    // ---- Mainloop --------------------------------------------------------
#pragma unroll 1
    for (int i = 0; i < NK; ++i) {
        const int slot = i % NSTAGE;
        asm volatile("cp.async.wait_group 1;" ::: "memory");
        __syncthreads();

        // STS dequant for chunk i+1 (group switch on even chunk numbers)
        if (((i + 1) & 1) == 0) { cur_s2 = pend_s2; cur_z2 = pend_z2; }
        if (i + 1 < NK) sts_dequant(bq, cur_s2, cur_z2, (i + 1) % NSTAGE);

        // prefetch for chunk i+2
        if (i + 2 < NK) {
            if (((i + 2) & 1) == 0) load_sz((i + 2) >> 1, pend_s2, pend_z2);
            ldg_packed(i + 2, bq);
            load_A(i + 2, (i + 2) % NSTAGE);
        }
        asm volatile("cp.async.commit_group;" ::: "memory");

        const uint32_t sA = sbase + slot * STAGE_BYTES;
        const uint32_t sB = sA + A_TILE_BYTES;

#pragma unroll
        for (int s = 0; s < 4; ++s) {   // 4 x k16 within KC=64
            uint32_t a[2][4], b[4][4];
#pragma unroll
            for (int mt = 0; mt < 2; ++mt)
                LDM_X4(a[mt], sA + aoff[mt] +
                              (uint32_t)((((s << 1) + achk) ^ asw[mt]) << 4));
#pragma unroll
            for (int nt = 0; nt < 4; ++nt)
                LDM_X4(b[nt], sB + boff[nt] +
                              (uint32_t)((((s << 1) + bchk) ^ bsw[nt]) << 4));
#pragma unroll
            for (int mt = 0; mt < 2; ++mt)
#pragma unroll
                for (int nt = 0; nt < 4; ++nt) {
                    mma16816(acc[mt][2 * nt],     a[mt], b[nt]);
                    mma16816(acc[mt][2 * nt + 1], a[mt], b[nt] + 2);
                }
        }
    }

    // ---- Epilogue: fp32 acc + bias + residual -> out ---------------------
    const int r  = lane >> 2;
    const int c2 = (lane & 3) * 2;
    const int mbase = tm_ * TM + warp_m * 32;
    const int nbase = tn_ * TN + warp_n * 64;
#pragma unroll
    for (int mt = 0; mt < 2; ++mt) {
#pragma unroll
        for (int half = 0; half < 2; ++half) {   // rows r and r+8
            const size_t m = (size_t)(mbase + mt * 16 + r + half * 8);
            const float* rp = residual + m * NDIM + nbase;
            float* op = out + m * NDIM + nbase;
#pragma unroll
            for (int nt = 0; nt < 8; ++nt) {
                const int n = nt * 8 + c2;
                float2 res = *(const float2*)(rp + n);
                float2 bz  = *(const float2*)(bias + nbase + n);
                float2 o;
                o.x = acc[mt][nt][2 * half]     + bz.x + res.x;
                o.y = acc[mt][nt][2 * half + 1] + bz.y + res.y;
                *(float2*)(op + n) = o;
            }
        }
    }
}

// ---------------------------------------------------------------------------
extern "C" void kernel_launch(void* const* d_in, const int* in_sizes, int n_in,
                              void* d_out, int out_size) {
    const float* input    = (const float*)d_in[0];   // [2,4096,4096] f32
    const float* residual = (const float*)d_in[1];   // [2,4096,4096] f32
    const int*   qweight  = (const int*)d_in[2];     // [512,4096] i32
    const float* scales   = (const float*)d_in[3];   // [32,4096] f32
    const int*   qzeros   = (const int*)d_in[4];     // [32,512] i32
    const float* bias     = (const float*)d_in[5];   // [4096] f32
    float* out = (float*)d_out;

    cudaFuncSetAttribute(k_gemm, cudaFuncAttributeMaxDynamicSharedMemorySize,
                         SMEM_DYN);

    k_aconv<<<(MDIM * (size_t)KDIM) / 8 / 256, 256>>>(input);

    const int nblocks = (MDIM / TM) * (NDIM / TN);   // 2048
    k_gemm<<<nblocks, 256, SMEM_DYN>>>(residual, bias, out,
                                       qweight, scales, qzeros);
}

// round 6
// speedup vs baseline: 1.1415x; 1.1346x over previous
#include <cuda_runtime.h>
#include <cuda_fp16.h>
#include <cstdint>

// Problem dims
#define MDIM 8192   // B*S
#define NDIM 4096
#define KDIM 4096

// GEMM tiling
#define TM 128
#define TN 128
#define KC 64                        // 64 fp16 = 128B per row (swizzle atom)
#define NSTAGE 3
#define NK (KDIM / KC)               // 64
#define A_TILE_BYTES (TM * KC * 2)   // 16384
#define B_TILE_BYTES (TN * KC * 2)   // 16384
#define STAGE_BYTES (A_TILE_BYTES + B_TILE_BYTES)   // 32768
#define SMEM_DYN (NSTAGE * STAGE_BYTES)             // 98304

// Scratch (allocation-free rule: __device__ globals)
__device__ uint4 g_A16[(MDIM * (size_t)KDIM) / 8];   // fp16 A, [M, K]
__device__ uint4 g_W16[(NDIM * (size_t)KDIM) / 8];   // fp16 W^T, [N, K]

// ---------------------------------------------------------------------------
// helpers
// ---------------------------------------------------------------------------
__device__ __forceinline__ uint32_t smem_u32(const void* p) {
    uint32_t r;
    asm("{ .reg .u64 t; cvta.to.shared.u64 t, %1; cvt.u32.u64 %0, t; }"
        : "=r"(r) : "l"(p));
    return r;
}

__device__ __forceinline__ void cp_async16(uint32_t s, const void* g) {
    asm volatile("cp.async.cg.shared.global [%0], [%1], 16;"
                 :: "r"(s), "l"(__cvta_generic_to_global(g)) : "memory");
}

#define LDM_X4(r, addr)                                                        \
    asm volatile("ldmatrix.sync.aligned.m8n8.x4.shared.b16 {%0,%1,%2,%3}, [%4];" \
                 : "=r"((r)[0]), "=r"((r)[1]), "=r"((r)[2]), "=r"((r)[3])      \
                 : "r"(addr))

__device__ __forceinline__ void mma16816(float* d, const uint32_t* a,
                                         const uint32_t* b) {
    asm volatile(
        "mma.sync.aligned.m16n8k16.row.col.f32.f16.f16.f32 "
        "{%0,%1,%2,%3}, {%4,%5,%6,%7}, {%8,%9}, {%0,%1,%2,%3};"
        : "+f"(d[0]), "+f"(d[1]), "+f"(d[2]), "+f"(d[3])
        : "r"(a[0]), "r"(a[1]), "r"(a[2]), "r"(a[3]), "r"(b[0]), "r"(b[1]));
}

// ---------------------------------------------------------------------------
// Pre-pass 1: A fp32 -> fp16
// ---------------------------------------------------------------------------
__global__ void __launch_bounds__(256) k_aconv(const float* __restrict__ in) {
    size_t i = ((size_t)blockIdx.x * 256 + threadIdx.x) * 8;
    float4 a = *(const float4*)(in + i);
    float4 b = *(const float4*)(in + i + 4);
    union { __half2 h[4]; uint4 u; } pk;
    pk.h[0] = __floats2half2_rn(a.x, a.y);
    pk.h[1] = __floats2half2_rn(a.z, a.w);
    pk.h[2] = __floats2half2_rn(b.x, b.y);
    pk.h[3] = __floats2half2_rn(b.z, b.w);
    g_A16[i >> 3] = pk.u;
}

// ---------------------------------------------------------------------------
// Pre-pass 2: GPTQ int4 dequant -> fp16, transposed to [N, K]
// w[k,n] = ((q[k/8,n] >> 4*(k%8)) & 15 - z[g,n]) * s[g,n],  g = k/128
// ---------------------------------------------------------------------------
__global__ void __launch_bounds__(256) k_dequant(const int* __restrict__ qw,
                                                 const float* __restrict__ sc,
                                                 const int* __restrict__ qz) {
    int idx = blockIdx.x * 256 + threadIdx.x;   // over (K/8)*N, n fastest
    int n  = idx & (NDIM - 1);
    int kk = idx >> 12;                         // k/8
    int g  = kk >> 4;                           // group = (kk*8)/128
    int q  = qw[idx];
    int zw = qz[(g << 9) | (n >> 3)];
    float z = (float)((zw >> ((n & 7) << 2)) & 15);
    float s = sc[(g << 12) | n];
    union { __half2 h[4]; uint4 u; } pk;
#pragma unroll
    for (int j = 0; j < 4; ++j) {
        float w0 = ((float)((q >> (8 * j))     & 15) - z) * s;
        float w1 = ((float)((q >> (8 * j + 4)) & 15) - z) * s;
        pk.h[j] = __floats2half2_rn(w0, w1);
    }
    __half* W = (__half*)g_W16;
    *(uint4*)(W + (size_t)n * KDIM + kk * 8) = pk.u;
}

// ---------------------------------------------------------------------------
// Main GEMM: C = A @ W^T + bias + residual
// 128x128 CTA tile, 8 warps (4m x 2n), warp tile 32x64, mma.sync m16n8k16,
// 3-stage cp.async pipeline, ping-pong fragment buffers so next k16-step's
// LDSMs issue under the current step's MMA shadow.
// ---------------------------------------------------------------------------
__global__ void __launch_bounds__(256, 2)
k_gemm(const float* __restrict__ residual, const float* __restrict__ bias,
       float* __restrict__ out) {
    extern __shared__ char smem_raw[];
    const uint32_t sbase = smem_u32(smem_raw);

    const int tid  = threadIdx.x;
    const int wid  = tid >> 5;
    const int lane = tid & 31;
    const int warp_m = wid & 3;   // 4 warps along M (32 rows each)
    const int warp_n = wid >> 2;  // 2 warps along N (64 cols each)

    // L2-friendly raster: supertiles of 8 m-tiles x 32 n-tiles
    const int bid = blockIdx.x;
    const int tm_ = ((bid >> 8) << 3) | (bid & 7);
    const int tn_ = (bid >> 3) & 31;

    const __half* A16 = (const __half*)g_A16;
    const __half* W16 = (const __half*)g_W16;
    const __half* gA = A16 + (size_t)tm_ * TM * KDIM;
    const __half* gB = W16 + (size_t)tn_ * TN * KDIM;

    // ldmatrix per-lane metadata
    const int tileid = lane >> 3, r8 = lane & 7;
    uint32_t aoff[2]; int asw[2];
    const int achk = tileid >> 1;
#pragma unroll
    for (int mt = 0; mt < 2; ++mt) {
        int ar = warp_m * 32 + mt * 16 + ((tileid & 1) << 3) + r8;
        aoff[mt] = (uint32_t)(ar << 7);
        asw[mt] = ar & 7;
    }
    uint32_t boff[4]; int bsw[4];
    const int bchk = tileid & 1;
#pragma unroll
    for (int nt = 0; nt < 4; ++nt) {
        int br = warp_n * 64 + nt * 16 + ((tileid >> 1) << 3) + r8;
        boff[nt] = (uint32_t)(br << 7);
        bsw[nt] = br & 7;
    }

    // Stage loader: 256 rows x 8 sixteen-byte cols = 2048 ops / 256 thr
    auto load_stage = [&](int c, int slot) {
        const uint32_t sA = sbase + slot * STAGE_BYTES;
        const __half* pA = gA + c * KC;
        const __half* pB = gB + c * KC;
#pragma unroll
        for (int rep = 0; rep < 4; ++rep) {
            int idx = tid + rep * 256;
            int row = idx >> 3;
            int c16 = idx & 7;
            uint32_t soff = (uint32_t)(row << 7) |
                            (uint32_t)((c16 ^ (row & 7)) << 4);
            cp_async16(sA + soff, pA + (size_t)row * KDIM + c16 * 8);
            cp_async16(sA + A_TILE_BYTES + soff, pB + (size_t)row * KDIM + c16 * 8);
        }
    };

    float acc[2][8][4];
#pragma unroll
    for (int mt = 0; mt < 2; ++mt)
#pragma unroll
        for (int nt = 0; nt < 8; ++nt)
#pragma unroll
            for (int j = 0; j < 4; ++j) acc[mt][nt][j] = 0.f;

    // Fragment load for k16 step s from stage (sA, sB)
#define LOAD_FRAGS(aa, bb, sA_, sB_, s)                                        \
    do {                                                                       \
        LDM_X4(aa[0], (sA_) + aoff[0] +                                        \
                      (uint32_t)(((((s) << 1) + achk) ^ asw[0]) << 4));        \
        LDM_X4(aa[1], (sA_) + aoff[1] +                                        \
                      (uint32_t)(((((s) << 1) + achk) ^ asw[1]) << 4));        \
        LDM_X4(bb[0], (sB_) + boff[0] +                                        \
                      (uint32_t)(((((s) << 1) + bchk) ^ bsw[0]) << 4));        \
        LDM_X4(bb[1], (sB_) + boff[1] +                                        \
                      (uint32_t)(((((s) << 1) + bchk) ^ bsw[1]) << 4));        \
        LDM_X4(bb[2], (sB_) + boff[2] +                                        \
                      (uint32_t)(((((s) << 1) + bchk) ^ bsw[2]) << 4));        \
        LDM_X4(bb[3], (sB_) + boff[3] +                                        \
                      (uint32_t)(((((s) << 1) + bchk) ^ bsw[3]) << 4));        \
    } while (0)

#define MMA_ALL(aa, bb)                                                        \
    do {                                                                       \
        _Pragma("unroll")                                                      \
        for (int mt = 0; mt < 2; ++mt)                                         \
            _Pragma("unroll")                                                  \
            for (int nt = 0; nt < 4; ++nt) {                                   \
                mma16816(acc[mt][2 * nt],     aa[mt], bb[nt]);                 \
                mma16816(acc[mt][2 * nt + 1], aa[mt], bb[nt] + 2);             \
            }                                                                  \
    } while (0)

    // Prologue
#pragma unroll
    for (int c = 0; c < NSTAGE - 1; ++c) {
        load_stage(c, c);
        asm volatile("cp.async.commit_group;" ::: "memory");
    }

#pragma unroll 1
    for (int i = 0; i < NK; ++i) {
        const int slot = i % NSTAGE;
        asm volatile("cp.async.wait_group 1;" ::: "memory");
        __syncthreads();

        const uint32_t sA = sbase + slot * STAGE_BYTES;
        const uint32_t sB = sA + A_TILE_BYTES;

        uint32_t a0[2][4], b0[4][4], a1[2][4], b1[4][4];
        // get step-0 fragments in flight immediately after the barrier
        LOAD_FRAGS(a0, b0, sA, sB, 0);

        // issue next-stage global loads under the LDSM/MMA shadow
        const int c = i + NSTAGE - 1;
        if (c < NK) load_stage(c, c % NSTAGE);
        asm volatile("cp.async.commit_group;" ::: "memory");

        // ping-pong: prefetch step s+1 fragments before step s MMAs
        LOAD_FRAGS(a1, b1, sA, sB, 1);
        MMA_ALL(a0, b0);
        LOAD_FRAGS(a0, b0, sA, sB, 2);
        MMA_ALL(a1, b1);
        LOAD_FRAGS(a1, b1, sA, sB, 3);
        MMA_ALL(a0, b0);
        MMA_ALL(a1, b1);
    }

    // Epilogue: fp32 acc + bias + residual -> out
    const int r  = lane >> 2;
    const int c2 = (lane & 3) * 2;
    const int mbase = tm_ * TM + warp_m * 32;
    const int nbase = tn_ * TN + warp_n * 64;
#pragma unroll
    for (int mt = 0; mt < 2; ++mt) {
#pragma unroll
        for (int half = 0; half < 2; ++half) {   // rows r and r+8
            const size_t m = (size_t)(mbase + mt * 16 + r + half * 8);
            const float* rp = residual + m * NDIM + nbase;
            float* op = out + m * NDIM + nbase;
#pragma unroll
            for (int nt = 0; nt < 8; ++nt) {
                const int n = nt * 8 + c2;
                float2 res = *(const float2*)(rp + n);
                float2 bz  = *(const float2*)(bias + nbase + n);
                float2 o;
                o.x = acc[mt][nt][2 * half]     + bz.x + res.x;
                o.y = acc[mt][nt][2 * half + 1] + bz.y + res.y;
                *(float2*)(op + n) = o;
            }
        }
    }
}

// ---------------------------------------------------------------------------
extern "C" void kernel_launch(void* const* d_in, const int* in_sizes, int n_in,
                              void* d_out, int out_size) {
    const float* input    = (const float*)d_in[0];   // [2,4096,4096] f32
    const float* residual = (const float*)d_in[1];   // [2,4096,4096] f32
    const int*   qweight  = (const int*)d_in[2];     // [512,4096] i32
    const float* scales   = (const float*)d_in[3];   // [32,4096] f32
    const int*   qzeros   = (const int*)d_in[4];     // [32,512] i32
    const float* bias     = (const float*)d_in[5];   // [4096] f32
    float* out = (float*)d_out;

    cudaFuncSetAttribute(k_gemm, cudaFuncAttributeMaxDynamicSharedMemorySize,
                         SMEM_DYN);

    k_aconv<<<(MDIM * (size_t)KDIM) / 8 / 256, 256>>>(input);
    k_dequant<<<(KDIM / 8) * NDIM / 256, 256>>>(qweight, scales, qzeros);

    const int nblocks = (MDIM / TM) * (NDIM / TN);   // 2048
    k_gemm<<<nblocks, 256, SMEM_DYN>>>(residual, bias, out);
}

// round 7
// speedup vs baseline: 1.2605x; 1.1043x over previous
#include <cuda_runtime.h>
#include <cuda_fp16.h>
#include <cstdint>

// Problem dims
#define MDIM 8192   // B*S
#define NDIM 4096
#define KDIM 4096

// GEMM tiling
#define TM 128
#define TN 128
#define KC 64                        // 64 fp16 = 128B per row (swizzle atom)
#define NSTAGE 3
#define NK (KDIM / KC)               // 64
#define A_TILE_BYTES (TM * KC * 2)   // 16384
#define B_TILE_BYTES (TN * KC * 2)   // 16384
#define STAGE_BYTES (A_TILE_BYTES + B_TILE_BYTES)   // 32768
#define SMEM_DYN (NSTAGE * STAGE_BYTES)             // 98304

// Scratch (allocation-free rule: __device__ globals)
__device__ uint4 g_A16[(MDIM * (size_t)KDIM) / 8];   // fp16 A, [M, K]
__device__ uint4 g_W16[(NDIM * (size_t)KDIM) / 8];   // fp16 W^T, [N, K]

// ---------------------------------------------------------------------------
// helpers
// ---------------------------------------------------------------------------
__device__ __forceinline__ uint32_t smem_u32(const void* p) {
    uint32_t r;
    asm("{ .reg .u64 t; cvta.to.shared.u64 t, %1; cvt.u32.u64 %0, t; }"
        : "=r"(r) : "l"(p));
    return r;
}

__device__ __forceinline__ void cp_async16(uint32_t s, const void* g) {
    asm volatile("cp.async.cg.shared.global [%0], [%1], 16;"
                 :: "r"(s), "l"(__cvta_generic_to_global(g)) : "memory");
}

#define LDM_X4(r, addr)                                                        \
    asm volatile("ldmatrix.sync.aligned.m8n8.x4.shared.b16 {%0,%1,%2,%3}, [%4];" \
                 : "=r"((r)[0]), "=r"((r)[1]), "=r"((r)[2]), "=r"((r)[3])      \
                 : "r"(addr))

__device__ __forceinline__ void mma16816(float* d, const uint32_t* a,
                                         const uint32_t* b) {
    asm volatile(
        "mma.sync.aligned.m16n8k16.row.col.f32.f16.f16.f32 "
        "{%0,%1,%2,%3}, {%4,%5,%6,%7}, {%8,%9}, {%0,%1,%2,%3};"
        : "+f"(d[0]), "+f"(d[1]), "+f"(d[2]), "+f"(d[3])
        : "r"(a[0]), "r"(a[1]), "r"(a[2]), "r"(a[3]), "r"(b[0]), "r"(b[1]));
}

// ---------------------------------------------------------------------------
// Pre-pass 1: A fp32 -> fp16
// ---------------------------------------------------------------------------
__global__ void __launch_bounds__(256) k_aconv(const float* __restrict__ in) {
    size_t i = ((size_t)blockIdx.x * 256 + threadIdx.x) * 8;
    float4 a = *(const float4*)(in + i);
    float4 b = *(const float4*)(in + i + 4);
    union { __half2 h[4]; uint4 u; } pk;
    pk.h[0] = __floats2half2_rn(a.x, a.y);
    pk.h[1] = __floats2half2_rn(a.z, a.w);
    pk.h[2] = __floats2half2_rn(b.x, b.y);
    pk.h[3] = __floats2half2_rn(b.z, b.w);
    g_A16[i >> 3] = pk.u;
}

// ---------------------------------------------------------------------------
// Pre-pass 2: GPTQ int4 dequant -> fp16, transposed to [N, K]
// w[k,n] = ((q[k/8,n] >> 4*(k%8)) & 15 - z[g,n]) * s[g,n],  g = k/128
// ---------------------------------------------------------------------------
__global__ void __launch_bounds__(256) k_dequant(const int* __restrict__ qw,
                                                 const float* __restrict__ sc,
                                                 const int* __restrict__ qz) {
    int idx = blockIdx.x * 256 + threadIdx.x;   // over (K/8)*N, n fastest
    int n  = idx & (NDIM - 1);
    int kk = idx >> 12;                         // k/8
    int g  = kk >> 4;                           // group = (kk*8)/128
    int q  = qw[idx];
    int zw = qz[(g << 9) | (n >> 3)];
    float z = (float)((zw >> ((n & 7) << 2)) & 15);
    float s = sc[(g << 12) | n];
    union { __half2 h[4]; uint4 u; } pk;
#pragma unroll
    for (int j = 0; j < 4; ++j) {
        float w0 = ((float)((q >> (8 * j))     & 15) - z) * s;
        float w1 = ((float)((q >> (8 * j + 4)) & 15) - z) * s;
        pk.h[j] = __floats2half2_rn(w0, w1);
    }
    __half* W = (__half*)g_W16;
    *(uint4*)(W + (size_t)n * KDIM + kk * 8) = pk.u;
}

// ---------------------------------------------------------------------------
// Main GEMM: C = A @ W^T + bias + residual
// 128x128 CTA tile, 8 warps (4m x 2n), warp tile 32x64, mma.sync m16n8k16,
// 3-stage cp.async pipeline. Software pipeline: B ping-pong + split-A reload
// within the chunk; barrier moved to iter end with next-stage step-0 fragment
// preload (stage i+1 is resident after wait_group 1 there).
// ---------------------------------------------------------------------------
__global__ void __launch_bounds__(256, 2)
k_gemm(const float* __restrict__ residual, const float* __restrict__ bias,
       float* __restrict__ out) {
    extern __shared__ char smem_raw[];
    const uint32_t sbase = smem_u32(smem_raw);

    const int tid  = threadIdx.x;
    const int wid  = tid >> 5;
    const int lane = tid & 31;
    const int warp_m = wid & 3;   // 4 warps along M (32 rows each)
    const int warp_n = wid >> 2;  // 2 warps along N (64 cols each)

    // L2-friendly raster: supertiles of 8 m-tiles x 32 n-tiles
    const int bid = blockIdx.x;
    const int tm_ = ((bid >> 8) << 3) | (bid & 7);
    const int tn_ = (bid >> 3) & 31;

    const __half* A16 = (const __half*)g_A16;
    const __half* W16 = (const __half*)g_W16;
    const __half* gA = A16 + (size_t)tm_ * TM * KDIM;
    const __half* gB = W16 + (size_t)tn_ * TN * KDIM;

    // ldmatrix per-lane metadata
    const int tileid = lane >> 3, r8 = lane & 7;
    uint32_t aoff[2]; int asw[2];
    const int achk = tileid >> 1;
#pragma unroll
    for (int mt = 0; mt < 2; ++mt) {
        int ar = warp_m * 32 + mt * 16 + ((tileid & 1) << 3) + r8;
        aoff[mt] = (uint32_t)(ar << 7);
        asw[mt] = ar & 7;
    }
    uint32_t boff[4]; int bsw[4];
    const int bchk = tileid & 1;
#pragma unroll
    for (int nt = 0; nt < 4; ++nt) {
        int br = warp_n * 64 + nt * 16 + ((tileid >> 1) << 3) + r8;
        boff[nt] = (uint32_t)(br << 7);
        bsw[nt] = br & 7;
    }

    // Stage loader: 256 rows x 8 sixteen-byte cols = 2048 ops / 256 thr
    auto load_stage = [&](int c, int slot) {
        const uint32_t sA = sbase + slot * STAGE_BYTES;
        const __half* pA = gA + c * KC;
        const __half* pB = gB + c * KC;
#pragma unroll
        for (int rep = 0; rep < 4; ++rep) {
            int idx = tid + rep * 256;
            int row = idx >> 3;
            int c16 = idx & 7;
            uint32_t soff = (uint32_t)(row << 7) |
                            (uint32_t)((c16 ^ (row & 7)) << 4);
            cp_async16(sA + soff, pA + (size_t)row * KDIM + c16 * 8);
            cp_async16(sA + A_TILE_BYTES + soff, pB + (size_t)row * KDIM + c16 * 8);
        }
    };

    float acc[2][8][4];
#pragma unroll
    for (int mt = 0; mt < 2; ++mt)
#pragma unroll
        for (int nt = 0; nt < 8; ++nt)
#pragma unroll
            for (int j = 0; j < 4; ++j) acc[mt][nt][j] = 0.f;

    // Fragment-load macros (step s from a stage base)
#define LOAD_BV(bb, sB_, s)                                                    \
    do {                                                                       \
        LDM_X4((bb)[0], (sB_) + boff[0] +                                      \
               (uint32_t)(((((s) << 1) + bchk) ^ bsw[0]) << 4));               \
        LDM_X4((bb)[1], (sB_) + boff[1] +                                      \
               (uint32_t)(((((s) << 1) + bchk) ^ bsw[1]) << 4));               \
        LDM_X4((bb)[2], (sB_) + boff[2] +                                      \
               (uint32_t)(((((s) << 1) + bchk) ^ bsw[2]) << 4));               \
        LDM_X4((bb)[3], (sB_) + boff[3] +                                      \
               (uint32_t)(((((s) << 1) + bchk) ^ bsw[3]) << 4));               \
    } while (0)

#define LOAD_AV(aa, idx, sA_, s)                                               \
    LDM_X4((aa), (sA_) + aoff[idx] +                                           \
           (uint32_t)(((((s) << 1) + achk) ^ asw[idx]) << 4))

#define MMA_MT(mt, aa, bb)                                                     \
    do {                                                                       \
        _Pragma("unroll")                                                      \
        for (int nt = 0; nt < 4; ++nt) {                                       \
            mma16816(acc[mt][2 * nt],     (aa), (bb)[nt]);                     \
            mma16816(acc[mt][2 * nt + 1], (aa), (bb)[nt] + 2);                 \
        }                                                                      \
    } while (0)

    // Prologue: stages 0 and 1 in flight, then step-0 fragments of stage 0
    load_stage(0, 0);
    asm volatile("cp.async.commit_group;" ::: "memory");
    load_stage(1, 1);
    asm volatile("cp.async.commit_group;" ::: "memory");
    asm volatile("cp.async.wait_group 1;" ::: "memory");
    __syncthreads();

    uint32_t a0[4], a1[4], b0[4][4], b1[4][4];
    LOAD_BV(b0, sbase + A_TILE_BYTES, 0);
    LOAD_AV(a0, 0, sbase, 0);
    LOAD_AV(a1, 1, sbase, 0);

#pragma unroll 1
    for (int i = 0; i < NK; ++i) {
        const uint32_t sAc = sbase + (i % NSTAGE) * STAGE_BYTES;
        const uint32_t sBc = sAc + A_TILE_BYTES;

        const int cn = i + 2;
        if (cn < NK) load_stage(cn, cn % NSTAGE);
        asm volatile("cp.async.commit_group;" ::: "memory");

        // step 0 (uses b0, a0/a1 preloaded)
        LOAD_BV(b1, sBc, 1);
        MMA_MT(0, a0, b0);
        LOAD_AV(a0, 0, sAc, 1);
        MMA_MT(1, a1, b0);
        LOAD_AV(a1, 1, sAc, 1);
        // step 1 (uses b1)
        LOAD_BV(b0, sBc, 2);
        MMA_MT(0, a0, b1);
        LOAD_AV(a0, 0, sAc, 2);
        MMA_MT(1, a1, b1);
        LOAD_AV(a1, 1, sAc, 2);
        // step 2 (uses b0)
        LOAD_BV(b1, sBc, 3);
        MMA_MT(0, a0, b0);
        LOAD_AV(a0, 0, sAc, 3);
        MMA_MT(1, a1, b0);
        LOAD_AV(a1, 1, sAc, 3);
        // step 3 (uses b1)
        MMA_MT(0, a0, b1);
        MMA_MT(1, a1, b1);

        // barrier at iter end: stage i+1 resident afterwards (one group pending)
        asm volatile("cp.async.wait_group 1;" ::: "memory");
        __syncthreads();

        // preload step-0 fragments of stage i+1 so next iter opens with MMAs
        if (i + 1 < NK) {
            const uint32_t sAn = sbase + ((i + 1) % NSTAGE) * STAGE_BYTES;
            LOAD_BV(b0, sAn + A_TILE_BYTES, 0);
            LOAD_AV(a0, 0, sAn, 0);
            LOAD_AV(a1, 1, sAn, 0);
        }
    }

    // Epilogue: fp32 acc + bias + residual -> out
    const int r  = lane >> 2;
    const int c2 = (lane & 3) * 2;
    const int mbase = tm_ * TM + warp_m * 32;
    const int nbase = tn_ * TN + warp_n * 64;
#pragma unroll
    for (int mt = 0; mt < 2; ++mt) {
#pragma unroll
        for (int half = 0; half < 2; ++half) {   // rows r and r+8
            const size_t m = (size_t)(mbase + mt * 16 + r + half * 8);
            const float* rp = residual + m * NDIM + nbase;
            float* op = out + m * NDIM + nbase;
#pragma unroll
            for (int nt = 0; nt < 8; ++nt) {
                const int n = nt * 8 + c2;
                float2 res = *(const float2*)(rp + n);
                float2 bz  = *(const float2*)(bias + nbase + n);
                float2 o;
                o.x = acc[mt][nt][2 * half]     + bz.x + res.x;
                o.y = acc[mt][nt][2 * half + 1] + bz.y + res.y;
                *(float2*)(op + n) = o;
            }
        }
    }
}

// ---------------------------------------------------------------------------
extern "C" void kernel_launch(void* const* d_in, const int* in_sizes, int n_in,
                              void* d_out, int out_size) {
    const float* input    = (const float*)d_in[0];   // [2,4096,4096] f32
    const float* residual = (const float*)d_in[1];   // [2,4096,4096] f32
    const int*   qweight  = (const int*)d_in[2];     // [512,4096] i32
    const float* scales   = (const float*)d_in[3];   // [32,4096] f32
    const int*   qzeros   = (const int*)d_in[4];     // [32,512] i32
    const float* bias     = (const float*)d_in[5];   // [4096] f32
    float* out = (float*)d_out;

    cudaFuncSetAttribute(k_gemm, cudaFuncAttributeMaxDynamicSharedMemorySize,
                         SMEM_DYN);

    k_aconv<<<(MDIM * (size_t)KDIM) / 8 / 256, 256>>>(input);
    k_dequant<<<(KDIM / 8) * NDIM / 256, 256>>>(qweight, scales, qzeros);

    const int nblocks = (MDIM / TM) * (NDIM / TN);   // 2048
    k_gemm<<<nblocks, 256, SMEM_DYN>>>(residual, bias, out);
}

// round 8
// speedup vs baseline: 1.2790x; 1.0146x over previous
#include <cuda_runtime.h>
#include <cuda_fp16.h>
#include <cstdint>

// Problem dims
#define MDIM 8192   // B*S
#define NDIM 4096
#define KDIM 4096

// GEMM tiling
#define TM 128
#define TN 128
#define KC 64                        // 64 fp16 = 128B per row (swizzle atom)
#define NSTAGE 3
#define NK (KDIM / KC)               // 64
#define A_TILE_BYTES (TM * KC * 2)   // 16384
#define B_TILE_BYTES (TN * KC * 2)   // 16384
#define STAGE_BYTES (A_TILE_BYTES + B_TILE_BYTES)   // 32768
#define SMEM_DYN (NSTAGE * STAGE_BYTES)             // 98304

// Pre-pass grid split
#define ACONV_BLOCKS ((MDIM * KDIM / 8) / 256)      // 16384
#define DEQ_BLOCKS   (((KDIM / 8) * NDIM) / 256)    // 8192

// Scratch (allocation-free rule: __device__ globals)
__device__ uint4 g_A16[(MDIM * (size_t)KDIM) / 8];   // fp16 A, [M, K]
__device__ uint4 g_W16[(NDIM * (size_t)KDIM) / 8];   // fp16 W^T, [N, K]

// ---------------------------------------------------------------------------
// helpers
// ---------------------------------------------------------------------------
__device__ __forceinline__ uint32_t smem_u32(const void* p) {
    uint32_t r;
    asm("{ .reg .u64 t; cvta.to.shared.u64 t, %1; cvt.u32.u64 %0, t; }"
        : "=r"(r) : "l"(p));
    return r;
}

__device__ __forceinline__ void cp_async16(uint32_t s, const void* g) {
    asm volatile("cp.async.cg.shared.global [%0], [%1], 16;"
                 :: "r"(s), "l"(__cvta_generic_to_global(g)) : "memory");
}

#define LDM_X4(r, addr)                                                        \
    asm volatile("ldmatrix.sync.aligned.m8n8.x4.shared.b16 {%0,%1,%2,%3}, [%4];" \
                 : "=r"((r)[0]), "=r"((r)[1]), "=r"((r)[2]), "=r"((r)[3])      \
                 : "r"(addr))

__device__ __forceinline__ void mma16816(float* d, const uint32_t* a,
                                         const uint32_t* b) {
    asm volatile(
        "mma.sync.aligned.m16n8k16.row.col.f32.f16.f16.f32 "
        "{%0,%1,%2,%3}, {%4,%5,%6,%7}, {%8,%9}, {%0,%1,%2,%3};"
        : "+f"(d[0]), "+f"(d[1]), "+f"(d[2]), "+f"(d[3])
        : "r"(a[0]), "r"(a[1]), "r"(a[2]), "r"(a[3]), "r"(b[0]), "r"(b[1]));
}

// ---------------------------------------------------------------------------
// Merged pre-pass: blocks [0, ACONV_BLOCKS) convert A fp32->fp16;
// blocks [ACONV_BLOCKS, ...) dequant GPTQ int4 -> fp16 W^T [N, K].
// ---------------------------------------------------------------------------
__global__ void __launch_bounds__(256)
k_pre(const float* __restrict__ in, const int* __restrict__ qw,
      const float* __restrict__ sc, const int* __restrict__ qz) {
    if (blockIdx.x < ACONV_BLOCKS) {
        size_t i = ((size_t)blockIdx.x * 256 + threadIdx.x) * 8;
        float4 a = *(const float4*)(in + i);
        float4 b = *(const float4*)(in + i + 4);
        union { __half2 h[4]; uint4 u; } pk;
        pk.h[0] = __floats2half2_rn(a.x, a.y);
        pk.h[1] = __floats2half2_rn(a.z, a.w);
        pk.h[2] = __floats2half2_rn(b.x, b.y);
        pk.h[3] = __floats2half2_rn(b.z, b.w);
        g_A16[i >> 3] = pk.u;
    } else {
        // w[k,n] = ((q[k/8,n] >> 4*(k%8)) & 15 - z[g,n]) * s[g,n], g = k/128
        int idx = (blockIdx.x - ACONV_BLOCKS) * 256 + threadIdx.x;
        int n  = idx & (NDIM - 1);
        int kk = idx >> 12;                         // k/8
        int g  = kk >> 4;                           // group = (kk*8)/128
        int q  = qw[idx];
        int zw = qz[(g << 9) | (n >> 3)];
        float z = (float)((zw >> ((n & 7) << 2)) & 15);
        float s = sc[(g << 12) | n];
        union { __half2 h[4]; uint4 u; } pk;
#pragma unroll
        for (int j = 0; j < 4; ++j) {
            float w0 = ((float)((q >> (8 * j))     & 15) - z) * s;
            float w1 = ((float)((q >> (8 * j + 4)) & 15) - z) * s;
            pk.h[j] = __floats2half2_rn(w0, w1);
        }
        __half* W = (__half*)g_W16;
        *(uint4*)(W + (size_t)n * KDIM + kk * 8) = pk.u;
    }
}

// ---------------------------------------------------------------------------
// Main GEMM: C = A @ W^T + bias + residual
// 128x128 CTA tile, 8 warps (4m x 2n), warp tile 32x64, mma.sync m16n8k16,
// 3-stage cp.async pipeline. B ping-pong + split-A fragment reload; the 8
// cp.async of the next stage are interleaved 2-at-a-time between MMA groups;
// barrier at iter end followed by next-stage step-0 fragment preload.
// ---------------------------------------------------------------------------
__global__ void __launch_bounds__(256, 2)
k_gemm(const float* __restrict__ residual, const float* __restrict__ bias,
       float* __restrict__ out) {
    extern __shared__ char smem_raw[];
    const uint32_t sbase = smem_u32(smem_raw);

    const int tid  = threadIdx.x;
    const int wid  = tid >> 5;
    const int lane = tid & 31;
    const int warp_m = wid & 3;   // 4 warps along M (32 rows each)
    const int warp_n = wid >> 2;  // 2 warps along N (64 cols each)

    // L2-friendly raster: supertiles of 8 m-tiles x 32 n-tiles
    const int bid = blockIdx.x;
    const int tm_ = ((bid >> 8) << 3) | (bid & 7);
    const int tn_ = (bid >> 3) & 31;

    const __half* A16 = (const __half*)g_A16;
    const __half* W16 = (const __half*)g_W16;
    const __half* gA = A16 + (size_t)tm_ * TM * KDIM;
    const __half* gB = W16 + (size_t)tn_ * TN * KDIM;

    // ldmatrix per-lane metadata
    const int tileid = lane >> 3, r8 = lane & 7;
    uint32_t aoff[2]; int asw[2];
    const int achk = tileid >> 1;
#pragma unroll
    for (int mt = 0; mt < 2; ++mt) {
        int ar = warp_m * 32 + mt * 16 + ((tileid & 1) << 3) + r8;
        aoff[mt] = (uint32_t)(ar << 7);
        asw[mt] = ar & 7;
    }
    uint32_t boff[4]; int bsw[4];
    const int bchk = tileid & 1;
#pragma unroll
    for (int nt = 0; nt < 4; ++nt) {
        int br = warp_n * 64 + nt * 16 + ((tileid >> 1) << 3) + r8;
        boff[nt] = (uint32_t)(br << 7);
        bsw[nt] = br & 7;
    }

    // Per-thread loader geometry: rep r covers row (tid>>3)+r*32 (0..255);
    // rows 0..127 = A half, 128..255 = B half (B starts at A_TILE_BYTES=128<<7).
    const int lrow0 = tid >> 3;
    const int lc16  = tid & 7;

    // Full-stage loader (prologue only)
    auto load_stage = [&](int c, int slot) {
        const uint32_t sA = sbase + slot * STAGE_BYTES;
        const __half* pA = gA + c * KC;
        const __half* pB = gB + c * KC;
#pragma unroll
        for (int rep = 0; rep < 8; ++rep) {
            int row = lrow0 + rep * 32;
            uint32_t soff = (uint32_t)(row << 7) |
                            (uint32_t)((lc16 ^ (row & 7)) << 4);
            const __half* g = (row < TM)
                ? pA + (size_t)row * KDIM + lc16 * 8
                : pB + (size_t)(row - TM) * KDIM + lc16 * 8;
            cp_async16(sA + soff, g);
        }
    };

    float acc[2][8][4];
#pragma unroll
    for (int mt = 0; mt < 2; ++mt)
#pragma unroll
        for (int nt = 0; nt < 8; ++nt)
#pragma unroll
            for (int j = 0; j < 4; ++j) acc[mt][nt][j] = 0.f;

#define LOAD_BV(bb, sB_, s)                                                    \
    do {                                                                       \
        LDM_X4((bb)[0], (sB_) + boff[0] +                                      \
               (uint32_t)(((((s) << 1) + bchk) ^ bsw[0]) << 4));               \
        LDM_X4((bb)[1], (sB_) + boff[1] +                                      \
               (uint32_t)(((((s) << 1) + bchk) ^ bsw[1]) << 4));               \
        LDM_X4((bb)[2], (sB_) + boff[2] +                                      \
               (uint32_t)(((((s) << 1) + bchk) ^ bsw[2]) << 4));               \
        LDM_X4((bb)[3], (sB_) + boff[3] +                                      \
               (uint32_t)(((((s) << 1) + bchk) ^ bsw[3]) << 4));               \
    } while (0)

#define LOAD_AV(aa, idx, sA_, s)                                               \
    LDM_X4((aa), (sA_) + aoff[idx] +                                           \
           (uint32_t)(((((s) << 1) + achk) ^ asw[idx]) << 4))

#define MMA_MT(mt, aa, bb)                                                     \
    do {                                                                       \
        _Pragma("unroll")                                                      \
        for (int nt = 0; nt < 4; ++nt) {                                       \
            mma16816(acc[mt][2 * nt],     (aa), (bb)[nt]);                     \
            mma16816(acc[mt][2 * nt + 1], (aa), (bb)[nt] + 2);                 \
        }                                                                      \
    } while (0)

    // Prologue: stages 0 and 1 in flight, then step-0 fragments of stage 0
    load_stage(0, 0);
    asm volatile("cp.async.commit_group;" ::: "memory");
    load_stage(1, 1);
    asm volatile("cp.async.commit_group;" ::: "memory");
    asm volatile("cp.async.wait_group 1;" ::: "memory");
    __syncthreads();

    uint32_t a0[4], a1[4], b0[4][4], b1[4][4];
    LOAD_BV(b0, sbase + A_TILE_BYTES, 0);
    LOAD_AV(a0, 0, sbase, 0);
    LOAD_AV(a1, 1, sbase, 0);

#pragma unroll 1
    for (int i = 0; i < NK; ++i) {
        const uint32_t sAc = sbase + (i % NSTAGE) * STAGE_BYTES;
        const uint32_t sBc = sAc + A_TILE_BYTES;

        const int cn = i + 2;
        const bool ld = (cn < NK);
        const uint32_t sdst = sbase + (cn % NSTAGE) * STAGE_BYTES;
        const __half* pA = gA + cn * KC;
        const __half* pB = gB + cn * KC;

        // 2 cp.async, interleaved between MMA groups
        auto cp2 = [&](int rep) {
#pragma unroll
            for (int r = rep; r < rep + 2; ++r) {
                int row = lrow0 + r * 32;
                uint32_t soff = (uint32_t)(row << 7) |
                                (uint32_t)((lc16 ^ (row & 7)) << 4);
                const __half* g = (row < TM)
                    ? pA + (size_t)row * KDIM + lc16 * 8
                    : pB + (size_t)(row - TM) * KDIM + lc16 * 8;
                cp_async16(sdst + soff, g);
            }
        };

        // step 0 (uses b0, a0/a1 preloaded)
        LOAD_BV(b1, sBc, 1);
        if (ld) cp2(0);
        MMA_MT(0, a0, b0);
        LOAD_AV(a0, 0, sAc, 1);
        if (ld) cp2(2);
        MMA_MT(1, a1, b0);
        LOAD_AV(a1, 1, sAc, 1);
        // step 1 (uses b1)
        LOAD_BV(b0, sBc, 2);
        if (ld) cp2(4);
        MMA_MT(0, a0, b1);
        LOAD_AV(a0, 0, sAc, 2);
        if (ld) cp2(6);
        MMA_MT(1, a1, b1);
        LOAD_AV(a1, 1, sAc, 2);
        asm volatile("cp.async.commit_group;" ::: "memory");
        // step 2 (uses b0)
        LOAD_BV(b1, sBc, 3);
        MMA_MT(0, a0, b0);
        LOAD_AV(a0, 0, sAc, 3);
        MMA_MT(1, a1, b0);
        LOAD_AV(a1, 1, sAc, 3);
        // step 3 (uses b1)
        MMA_MT(0, a0, b1);
        MMA_MT(1, a1, b1);

        // barrier at iter end: stage i+1 resident afterwards (1 group pending)
        asm volatile("cp.async.wait_group 1;" ::: "memory");
        __syncthreads();

        // preload step-0 fragments of stage i+1 so next iter opens with MMAs
        if (i + 1 < NK) {
            const uint32_t sAn = sbase + ((i + 1) % NSTAGE) * STAGE_BYTES;
            LOAD_BV(b0, sAn + A_TILE_BYTES, 0);
            LOAD_AV(a0, 0, sAn, 0);
            LOAD_AV(a1, 1, sAn, 0);
        }
    }

    // Epilogue: fp32 acc + bias + residual -> out
    const int r  = lane >> 2;
    const int c2 = (lane & 3) * 2;
    const int mbase = tm_ * TM + warp_m * 32;
    const int nbase = tn_ * TN + warp_n * 64;
#pragma unroll
    for (int mt = 0; mt < 2; ++mt) {
#pragma unroll
        for (int half = 0; half < 2; ++half) {   // rows r and r+8
            const size_t m = (size_t)(mbase + mt * 16 + r + half * 8);
            const float* rp = residual + m * NDIM + nbase;
            float* op = out + m * NDIM + nbase;
#pragma unroll
            for (int nt = 0; nt < 8; ++nt) {
                const int n = nt * 8 + c2;
                float2 res = *(const float2*)(rp + n);
                float2 bz  = *(const float2*)(bias + nbase + n);
                float2 o;
                o.x = acc[mt][nt][2 * half]     + bz.x + res.x;
                o.y = acc[mt][nt][2 * half + 1] + bz.y + res.y;
                *(float2*)(op + n) = o;
            }
        }
    }
}

// ---------------------------------------------------------------------------
extern "C" void kernel_launch(void* const* d_in, const int* in_sizes, int n_in,
                              void* d_out, int out_size) {
    const float* input    = (const float*)d_in[0];   // [2,4096,4096] f32
    const float* residual = (const float*)d_in[1];   // [2,4096,4096] f32
    const int*   qweight  = (const int*)d_in[2];     // [512,4096] i32
    const float* scales   = (const float*)d_in[3];   // [32,4096] f32
    const int*   qzeros   = (const int*)d_in[4];     // [32,512] i32
    const float* bias     = (const float*)d_in[5];   // [4096] f32
    float* out = (float*)d_out;

    cudaFuncSetAttribute(k_gemm, cudaFuncAttributeMaxDynamicSharedMemorySize,
                         SMEM_DYN);

    k_pre<<<ACONV_BLOCKS + DEQ_BLOCKS, 256>>>(input, qweight, scales, qzeros);

    const int nblocks = (MDIM / TM) * (NDIM / TN);   // 2048
    k_gemm<<<nblocks, 256, SMEM_DYN>>>(residual, bias, out);
}